// round 2
// baseline (speedup 1.0000x reference)
#include <cuda_runtime.h>

// Problem constants
#define Bb 4
#define Ss 4096
#define Dd 1024
#define MTOT (Bb * Ss)   // 16384

// ---------------------------------------------------------------------------
// Scratch (device globals; no allocation allowed)
// ---------------------------------------------------------------------------
__device__ float g_q  [(size_t)MTOT * Dd];   // q_phi   [B*S, D]
__device__ float g_k  [(size_t)MTOT * Dd];   // k_phi   [B*S, D]
__device__ float g_v  [(size_t)MTOT * Dd];   // v       [B*S, D]
__device__ float g_att[(size_t)MTOT * Dd];   // (q_phi @ kv) * z
__device__ float g_kv [(size_t)Bb * Dd * Dd];// kv      [B, D, D]
__device__ float g_ksum[Bb * Dd];            // k_sum   [B, D]
__device__ float g_z  [Bb * Ss];             // z       [B, S]

enum { EPI_NONE = 0, EPI_BIAS = 1, EPI_BIAS_PHI = 2, EPI_SCALE = 3, EPI_BIAS_RES = 4 };

// ---------------------------------------------------------------------------
// 128x128x8 SGEMM, 256 threads, 8x8 per thread (warp-split 4+4 layout,
// conflict-free smem reads), register prefetch of next K-tile.
//   C[M,N] = op(A) @ B  (+ epilogue)
//   TA=false: A is [M,K] row-major, lda = row stride
//   TA=true : logical A^T; physical A is [K,M] row-major, lda = row stride (=M)
//   B is [K,N] row-major, ldb = N. ldc = N.
// Batched via blockIdx.z with element strides sA/sB/sC (and sE for `extra`).
//   EPI_BIAS_PHI: C = phi(acc + bias[col]),  phi(x) = x>0 ? x+1 : exp(x)
//   EPI_BIAS    : C = acc + bias[col]
//   EPI_SCALE   : C = acc * extra[row]                  (extra = z, per batch)
//   EPI_BIAS_RES: C = acc + bias[col] + extra[row*N+col] (extra = residual)
// ---------------------------------------------------------------------------
template<int EPI, bool TA>
__global__ __launch_bounds__(256)
void sgemm_k(const float* __restrict__ A, const float* __restrict__ Bm,
             float* __restrict__ C, int M, int N, int K, int lda, int ldb,
             long long sA, long long sB, long long sC,
             const float* __restrict__ bias,
             const float* __restrict__ extra, long long sE)
{
    A  += (long long)blockIdx.z * sA;
    Bm += (long long)blockIdx.z * sB;
    C  += (long long)blockIdx.z * sC;
    const float* extraB = extra;
    if (EPI == EPI_SCALE) extraB = extra + (long long)blockIdx.z * sE;

    __shared__ float As[8][132];   // padded: conflict-light transpose stores
    __shared__ float Bs[8][128];

    const int tid  = threadIdx.x;
    const int w    = tid >> 5, lane = tid & 31;
    const int wR   = w >> 1,   wC   = w & 1;       // warps: 4 rows x 2 cols
    const int lR   = lane >> 3, lC  = lane & 7;    // lanes: 4 rows x 8 cols
    const int row0 = wR * 32 + lR * 4;             // + {0..3} and +16 +{0..3}
    const int col0 = wC * 64 + lC * 4;             // + {0..3} and +32 +{0..3}
    const int rBase = blockIdx.y * 128;
    const int cBase = blockIdx.x * 128;

    float acc[8][8];
    #pragma unroll
    for (int i = 0; i < 8; i++)
        #pragma unroll
        for (int j = 0; j < 8; j++) acc[i][j] = 0.f;

    // B tile loader: 8 rows x 128 cols, one float4 per thread
    const int bLr = tid >> 5;
    const int bLc = (tid & 31) * 4;
    const float* Bptr = Bm + (long long)bLr * ldb + cBase + bLc;

    // A tile loader
    int aLr, aLc;
    const float* Aptr;
    if (TA) {
        aLr = tid >> 5; aLc = (tid & 31) * 4;      // 8 rows x 128 cols of A-phys
        Aptr = A + (long long)aLr * lda + rBase + aLc;
    } else {
        aLr = tid >> 1; aLc = (tid & 1) * 4;       // 128 rows x 8 cols
        Aptr = A + (long long)(rBase + aLr) * lda + aLc;
    }

    const int nIter = K >> 3;
    float4 av = *(const float4*)Aptr;
    float4 bv = *(const float4*)Bptr;

    for (int it = 0; it < nIter; ++it) {
        __syncthreads();
        if (TA) {
            *(float4*)&As[aLr][aLc] = av;
        } else {
            As[aLc + 0][aLr] = av.x;
            As[aLc + 1][aLr] = av.y;
            As[aLc + 2][aLr] = av.z;
            As[aLc + 3][aLr] = av.w;
        }
        *(float4*)&Bs[bLr][bLc] = bv;
        __syncthreads();

        if (it + 1 < nIter) {                      // prefetch next tile
            if (TA) Aptr += (long long)8 * lda; else Aptr += 8;
            Bptr += (long long)8 * ldb;
            av = *(const float4*)Aptr;
            bv = *(const float4*)Bptr;
        }

        #pragma unroll
        for (int kk = 0; kk < 8; ++kk) {
            float a[8], b[8];
            *(float4*)&a[0] = *(const float4*)&As[kk][row0];
            *(float4*)&a[4] = *(const float4*)&As[kk][row0 + 16];
            *(float4*)&b[0] = *(const float4*)&Bs[kk][col0];
            *(float4*)&b[4] = *(const float4*)&Bs[kk][col0 + 32];
            #pragma unroll
            for (int i = 0; i < 8; i++)
                #pragma unroll
                for (int j = 0; j < 8; j++)
                    acc[i][j] = fmaf(a[i], b[j], acc[i][j]);
        }
    }

    // Epilogue
    #pragma unroll
    for (int i = 0; i < 8; i++) {
        const int gr = rBase + row0 + (i < 4 ? i : 16 + (i - 4));
        float zv = 0.f;
        if (EPI == EPI_SCALE) zv = extraB[gr];
        #pragma unroll
        for (int jj = 0; jj < 2; ++jj) {
            const int gc = cBase + col0 + jj * 32;
            float vals[4];
            #pragma unroll
            for (int j = 0; j < 4; j++) {
                float vv = acc[i][jj * 4 + j];
                const int c = gc + j;
                if (EPI == EPI_BIAS || EPI == EPI_BIAS_PHI || EPI == EPI_BIAS_RES)
                    vv += bias[c];
                if (EPI == EPI_BIAS_PHI)
                    vv = (vv > 0.f) ? (vv + 1.f) : __expf(vv);
                if (EPI == EPI_SCALE)
                    vv *= zv;
                if (EPI == EPI_BIAS_RES)
                    vv += extraB[(long long)gr * N + c];
                vals[j] = vv;
            }
            *(float4*)&C[(long long)gr * N + gc] =
                make_float4(vals[0], vals[1], vals[2], vals[3]);
        }
    }
}

// ---------------------------------------------------------------------------
// k_sum[b,d] = sum_s k_phi[b,s,d]   (atomic partial sums over 8 s-chunks)
// ---------------------------------------------------------------------------
__global__ void ksum_zero_k()
{
    g_ksum[blockIdx.x * 256 + threadIdx.x] = 0.f;
}

__global__ void ksum_k()
{
    const int b  = blockIdx.z;
    const int d  = blockIdx.x * 256 + threadIdx.x;
    const int s0 = blockIdx.y * (Ss / 8);
    const float* p = g_k + ((size_t)b * Ss + s0) * Dd + d;
    float a0 = 0.f, a1 = 0.f, a2 = 0.f, a3 = 0.f;
    #pragma unroll 4
    for (int s = 0; s < Ss / 8; s += 4) {
        a0 += p[(size_t)(s + 0) * Dd];
        a1 += p[(size_t)(s + 1) * Dd];
        a2 += p[(size_t)(s + 2) * Dd];
        a3 += p[(size_t)(s + 3) * Dd];
    }
    atomicAdd(&g_ksum[b * Dd + d], (a0 + a1) + (a2 + a3));
}

// ---------------------------------------------------------------------------
// z[b,s] = 1 / (dot(q_phi[b,s,:], k_sum[b,:]) + 1e-6), one warp per (b,s)
// ---------------------------------------------------------------------------
__global__ void z_k()
{
    const int gw   = (blockIdx.x * blockDim.x + threadIdx.x) >> 5;
    const int lane = threadIdx.x & 31;
    const int b    = gw >> 12;                 // S = 4096
    const float* qrow = g_q + (size_t)gw * Dd;
    const float* ks   = g_ksum + b * Dd;
    float s = 0.f;
    #pragma unroll
    for (int it = 0; it < Dd / 32; ++it) {
        const int d = it * 32 + lane;
        s += qrow[d] * ks[d];
    }
    #pragma unroll
    for (int o = 16; o; o >>= 1) s += __shfl_xor_sync(0xffffffffu, s, o);
    if (lane == 0) g_z[gw] = 1.0f / (s + 1e-6f);
}

// ---------------------------------------------------------------------------
// Launch
// ---------------------------------------------------------------------------
extern "C" void kernel_launch(void* const* d_in, const int* in_sizes, int n_in,
                              void* d_out, int out_size)
{
    (void)in_sizes; (void)n_in; (void)out_size;
    const float* inputs  = (const float*)d_in[0];
    const float* context = (const float*)d_in[1];
    const float* Wq = (const float*)d_in[2];
    const float* bq = (const float*)d_in[3];
    const float* Wk = (const float*)d_in[4];
    const float* bk = (const float*)d_in[5];
    const float* Wv = (const float*)d_in[6];
    const float* bv = (const float*)d_in[7];
    const float* Wo = (const float*)d_in[8];
    const float* bo = (const float*)d_in[9];
    float* out = (float*)d_out;

    float *q, *k, *v, *att, *kv;
    cudaGetSymbolAddress((void**)&q,   g_q);
    cudaGetSymbolAddress((void**)&k,   g_k);
    cudaGetSymbolAddress((void**)&v,   g_v);
    cudaGetSymbolAddress((void**)&att, g_att);
    cudaGetSymbolAddress((void**)&kv,  g_kv);
    float* zp;
    cudaGetSymbolAddress((void**)&zp,  g_z);

    const dim3 blk(256);
    const dim3 gProj(Dd / 128, MTOT / 128, 1);      // (8, 128)
    const dim3 gKV(Dd / 128, Dd / 128, Bb);         // (8, 8, 4)
    const dim3 gAtt(Dd / 128, Ss / 128, Bb);        // (8, 32, 4)

    // 1-3. Projections
    sgemm_k<EPI_BIAS_PHI, false><<<gProj, blk>>>(
        inputs,  Wq, q, MTOT, Dd, Dd, Dd, Dd, 0, 0, 0, bq, nullptr, 0);
    sgemm_k<EPI_BIAS_PHI, false><<<gProj, blk>>>(
        context, Wk, k, MTOT, Dd, Dd, Dd, Dd, 0, 0, 0, bk, nullptr, 0);
    sgemm_k<EPI_BIAS, false><<<gProj, blk>>>(
        context, Wv, v, MTOT, Dd, Dd, Dd, Dd, 0, 0, 0, bv, nullptr, 0);

    // 4. k_sum
    ksum_zero_k<<<(Bb * Dd) / 256, blk>>>();
    ksum_k<<<dim3(Dd / 256, 8, Bb), blk>>>();

    // 5. z
    z_k<<<(Bb * Ss * 32) / 256, blk>>>();

    // 6. kv[b] = k_phi[b]^T @ v[b]   (M=D, N=D, K=S; TA with lda = D)
    sgemm_k<EPI_NONE, true><<<gKV, blk>>>(
        k, v, kv, Dd, Dd, Ss, Dd, Dd,
        (long long)Ss * Dd, (long long)Ss * Dd, (long long)Dd * Dd,
        nullptr, nullptr, 0);

    // 7. att[b] = (q_phi[b] @ kv[b]) * z[b]
    sgemm_k<EPI_SCALE, false><<<gAtt, blk>>>(
        q, kv, att, Ss, Dd, Dd, Dd, Dd,
        (long long)Ss * Dd, (long long)Dd * Dd, (long long)Ss * Dd,
        nullptr, zp, (long long)Ss);

    // 8. out = att @ Wo + bo + inputs
    sgemm_k<EPI_BIAS_RES, false><<<gProj, blk>>>(
        att, Wo, out, MTOT, Dd, Dd, Dd, Dd, 0, 0, 0, bo, inputs, 0);
}

// round 4
// speedup vs baseline: 2.4685x; 2.4685x over previous
#include <cuda_runtime.h>
#include <cuda_bf16.h>
#include <stdint.h>

#define Bb 4
#define Ss 4096
#define Dd 1024
#define MTOT (Bb * Ss)   // 16384

// ---------------------------------------------------------------------------
// Scratch (device globals; allocation is forbidden)
// ---------------------------------------------------------------------------
__device__ __nv_bfloat16 g_ih [(size_t)MTOT * Dd], g_il [(size_t)MTOT * Dd]; // inputs split
__device__ __nv_bfloat16 g_ch [(size_t)MTOT * Dd], g_cl [(size_t)MTOT * Dd]; // context split
__device__ __nv_bfloat16 g_qh [(size_t)MTOT * Dd], g_ql [(size_t)MTOT * Dd]; // q_phi split
__device__ __nv_bfloat16 g_kTh[(size_t)Bb * Dd * Ss], g_kTl[(size_t)Bb * Dd * Ss]; // k_phi^T
__device__ __nv_bfloat16 g_vTh[(size_t)Bb * Dd * Ss], g_vTl[(size_t)Bb * Dd * Ss]; // v^T
__device__ __nv_bfloat16 g_ath[(size_t)MTOT * Dd], g_atl[(size_t)MTOT * Dd]; // att split
__device__ __nv_bfloat16 g_kvh[(size_t)Bb * Dd * Dd], g_kvl[(size_t)Bb * Dd * Dd]; // kv^T
__device__ __nv_bfloat16 g_WtH[(size_t)4 * Dd * Dd], g_WtL[(size_t)4 * Dd * Dd];   // W^T split
__device__ float g_ksum[Bb * Dd];
__device__ float g_z  [Bb * Ss];

// ---------------------------------------------------------------------------
// Helpers (baseline compute_103 instructions only: mma.sync / ldmatrix / cp.async)
// ---------------------------------------------------------------------------
static __device__ __forceinline__ uint32_t smem_u32(const void* p) {
    uint32_t a;
    asm("{ .reg .u64 t; cvta.to.shared.u64 t, %1; cvt.u32.u64 %0, t; }"
        : "=r"(a) : "l"(p));
    return a;
}

static __device__ __forceinline__ void ldsm4(uint32_t* r, uint32_t addr) {
    asm volatile("ldmatrix.sync.aligned.m8n8.x4.shared.b16 {%0,%1,%2,%3}, [%4];"
                 : "=r"(r[0]), "=r"(r[1]), "=r"(r[2]), "=r"(r[3]) : "r"(addr));
}

static __device__ __forceinline__ void mma16816(float* d, const uint32_t* a,
                                                const uint32_t* b) {
    asm volatile(
        "mma.sync.aligned.m16n8k16.row.col.f32.bf16.bf16.f32 "
        "{%0,%1,%2,%3}, {%4,%5,%6,%7}, {%8,%9}, {%0,%1,%2,%3};"
        : "+f"(d[0]), "+f"(d[1]), "+f"(d[2]), "+f"(d[3])
        : "r"(a[0]), "r"(a[1]), "r"(a[2]), "r"(a[3]), "r"(b[0]), "r"(b[1]));
}

#define CP16(dst, src) \
    asm volatile("cp.async.cg.shared.global [%0], [%1], 16;" :: "r"(dst), "l"(src))
#define CP_COMMIT() asm volatile("cp.async.commit_group;" ::: "memory")
#define CP_WAIT1()  asm volatile("cp.async.wait_group 1;" ::: "memory")

static __device__ __forceinline__ void split_bf16(float v, __nv_bfloat16& h, __nv_bfloat16& l) {
    h = __float2bfloat16(v);
    l = __float2bfloat16(v - __bfloat162float(h));
}
static __device__ __forceinline__ uint32_t pack2(__nv_bfloat16 a, __nv_bfloat16 b) {
    return (uint32_t)__bfloat16_as_ushort(a) | ((uint32_t)__bfloat16_as_ushort(b) << 16);
}

// ---------------------------------------------------------------------------
// Split-bf16 warp-MMA GEMM: C[128x128] = (Ah+Al) @ (Bh+Bl)^T
//   A: [M,K] K-major bf16 split; B: [N,K] K-major bf16 split.
//   CTA 128x128, K-chunk 64, 8 warps (4M x 2N), warp tile 32x64.
//   3-stage cp.async pipeline, xor-swizzled 128B smem rows, fp32 accum.
//   3 combos per chunk: AhBh + AlBh + AhBl.
// ---------------------------------------------------------------------------
enum { E_Q = 0, E_K = 1, E_V = 2, E_KVP = 3, E_ATT = 4, E_OUT = 5 };

#define TILE_B   16384            // 128 rows x 128B (128x64 bf16)
#define STAGE_B  (4 * TILE_B)     // Ah | Al | Bh | Bl
#define SMEM_DYN (3 * STAGE_B)    // 196608

template<int EPI>
__global__ __launch_bounds__(256, 1)
void mma_gemm(const __nv_bfloat16* __restrict__ Ah, const __nv_bfloat16* __restrict__ Al,
              const __nv_bfloat16* __restrict__ Bh, const __nv_bfloat16* __restrict__ Bl,
              int K, int lda, int ldb, long long sA, long long sB,
              const float* __restrict__ bias, const float* __restrict__ zarr,
              const float* __restrict__ resid, float* __restrict__ Cf,
              __nv_bfloat16* __restrict__ Ch, __nv_bfloat16* __restrict__ Cl)
{
    extern __shared__ __align__(1024) char dsm[];
    const uint32_t sbase = smem_u32(dsm);

    const int tid  = threadIdx.x;
    const int w    = tid >> 5, lane = tid & 31;
    const int wm0  = (w >> 1) * 32;     // warp M offset in CTA tile
    const int wn0  = (w & 1) * 64;      // warp N offset
    const int bz    = blockIdx.z;
    const int rbase = blockIdx.y * 128;
    const int cbase = blockIdx.x * 128;

    const __nv_bfloat16* pAh = Ah + (size_t)bz * sA;
    const __nv_bfloat16* pAl = Al + (size_t)bz * sA;
    const __nv_bfloat16* pBh = Bh + (size_t)bz * sB;
    const __nv_bfloat16* pBl = Bl + (size_t)bz * sB;

    float acc[2][8][4];
    #pragma unroll
    for (int a = 0; a < 2; a++)
        #pragma unroll
        for (int b = 0; b < 8; b++)
            #pragma unroll
            for (int c = 0; c < 4; c++) acc[a][b][c] = 0.f;

    // ---- stage loader: 4 tiles of 128 rows x 128B, xor-8 swizzle ----
    auto load_stage = [&](int stg, int it) {
        const uint32_t sb = sbase + stg * STAGE_B;
        const size_t k0 = (size_t)it * 64;
        #pragma unroll
        for (int i = 0; i < 4; i++) {
            const int row = (tid >> 3) + i * 32;
            const int u   = tid & 7;
            const uint32_t off = ((uint32_t)row << 7) + (uint32_t)((u ^ (row & 7)) << 4);
            const size_t ea = (size_t)(rbase + row) * lda + k0 + (size_t)u * 8;
            const size_t eb = (size_t)(cbase + row) * ldb + k0 + (size_t)u * 8;
            CP16(sb + off,              pAh + ea);
            CP16(sb + TILE_B + off,     pAl + ea);
            CP16(sb + 2 * TILE_B + off, pBh + eb);
            CP16(sb + 3 * TILE_B + off, pBl + eb);
        }
    };

    const int nch = K >> 6;
    load_stage(0, 0); CP_COMMIT();
    load_stage(1, 1); CP_COMMIT();

    // fragment address components
    const int la15 = lane & 15, la7 = lane & 7;
    const uint32_t aRowB = (uint32_t)(wm0 + la15) << 7;
    const int aSel = lane >> 4;                        // A 16B-chunk select
    const int bRow = wn0 + la7 + ((lane >> 1) & 8);    // B row within N-tile base
    const int bSel = (lane >> 3) & 1;                  // B 16B-chunk select

    for (int it = 0; it < nch; ++it) {
        CP_WAIT1();
        __syncthreads();
        if (it + 2 < nch) load_stage((it + 2) % 3, it + 2);
        CP_COMMIT();

        const uint32_t sb = sbase + (it % 3) * STAGE_B;
        #pragma unroll
        for (int ks = 0; ks < 4; ++ks) {
            uint32_t ah[2][4], al[2][4], bh[4][4], bl[4][4];
            #pragma unroll
            for (int mt = 0; mt < 2; mt++) {
                const uint32_t ad = sb + aRowB + (mt << 11)
                                  + (uint32_t)((((ks << 1) + aSel) ^ la7) << 4);
                ldsm4(ah[mt], ad);
                ldsm4(al[mt], ad + TILE_B);
            }
            #pragma unroll
            for (int nt = 0; nt < 4; nt++) {
                const uint32_t bd = sb + 2 * TILE_B
                                  + ((uint32_t)(bRow + (nt << 4)) << 7)
                                  + (uint32_t)((((ks << 1) + bSel) ^ la7) << 4);
                ldsm4(bh[nt], bd);
                ldsm4(bl[nt], bd + TILE_B);
            }
            #pragma unroll
            for (int mt = 0; mt < 2; mt++)
                #pragma unroll
                for (int nt = 0; nt < 4; nt++)
                    #pragma unroll
                    for (int s2 = 0; s2 < 2; s2++) {
                        float* d = acc[mt][nt * 2 + s2];
                        mma16816(d, ah[mt], &bh[nt][s2 * 2]);
                        mma16816(d, al[mt], &bh[nt][s2 * 2]);
                        mma16816(d, ah[mt], &bl[nt][s2 * 2]);
                    }
        }
    }

    // ------------------------------ epilogue -------------------------------
    const int rQ = lane >> 2;          // 0..7
    const int cP = (lane & 3) * 2;     // 0,2,4,6

    if (EPI == E_Q || EPI == E_ATT || EPI == E_OUT) {
        #pragma unroll
        for (int mt = 0; mt < 2; mt++)
            #pragma unroll
            for (int h = 0; h < 2; h++) {
                const int grow = rbase + wm0 + mt * 16 + rQ + h * 8;
                float zv = 1.f;
                if (EPI == E_ATT) zv = zarr[(size_t)bz * Ss + grow];
                #pragma unroll
                for (int nt8 = 0; nt8 < 8; nt8++) {
                    const int gcol = cbase + wn0 + nt8 * 8 + cP;
                    float v0 = acc[mt][nt8][h * 2 + 0];
                    float v1 = acc[mt][nt8][h * 2 + 1];
                    if (EPI == E_Q || EPI == E_OUT) {
                        v0 += bias[gcol];
                        v1 += bias[gcol + 1];
                    }
                    if (EPI == E_Q) {
                        v0 = (v0 > 0.f) ? (v0 + 1.f) : __expf(v0);
                        v1 = (v1 > 0.f) ? (v1 + 1.f) : __expf(v1);
                    }
                    if (EPI == E_ATT) { v0 *= zv; v1 *= zv; }
                    if (EPI == E_OUT) {
                        const size_t gi = (size_t)grow * Dd + gcol;
                        float2 rv = *(const float2*)(resid + gi);
                        *(float2*)(Cf + gi) = make_float2(v0 + rv.x, v1 + rv.y);
                    } else {
                        const size_t gi = (EPI == E_Q)
                            ? (size_t)grow * Dd + gcol
                            : ((size_t)bz * Ss + grow) * (size_t)Dd + gcol;
                        __nv_bfloat16 h0, l0, h1, l1;
                        split_bf16(v0, h0, l0);
                        split_bf16(v1, h1, l1);
                        *(uint32_t*)(Ch + gi) = pack2(h0, h1);
                        *(uint32_t*)(Cl + gi) = pack2(l0, l1);
                    }
                }
            }
    } else {
        // E_K / E_V / E_KVP: transpose via smem staging, coalesced stores
        __syncthreads();                      // all compute done; reuse dsm
        __nv_bfloat16* sTh = (__nv_bfloat16*)dsm;
        __nv_bfloat16* sTl = (__nv_bfloat16*)(dsm + 34816);   // 128*136*2
        #pragma unroll
        for (int mt = 0; mt < 2; mt++)
            #pragma unroll
            for (int h = 0; h < 2; h++) {
                const int r = wm0 + mt * 16 + rQ + h * 8;
                #pragma unroll
                for (int nt8 = 0; nt8 < 8; nt8++) {
                    const int c = wn0 + nt8 * 8 + cP;
                    float v0 = acc[mt][nt8][h * 2 + 0];
                    float v1 = acc[mt][nt8][h * 2 + 1];
                    if (EPI == E_K || EPI == E_V) {
                        v0 += bias[cbase + c];
                        v1 += bias[cbase + c + 1];
                    }
                    if (EPI == E_K) {
                        v0 = (v0 > 0.f) ? (v0 + 1.f) : __expf(v0);
                        v1 = (v1 > 0.f) ? (v1 + 1.f) : __expf(v1);
                    }
                    __nv_bfloat16 h0, l0, h1, l1;
                    split_bf16(v0, h0, l0);
                    split_bf16(v1, h1, l1);
                    sTh[c * 136 + r] = h0;       sTl[c * 136 + r] = l0;
                    sTh[(c + 1) * 136 + r] = h1; sTl[(c + 1) * 136 + r] = l1;
                }
            }
        __syncthreads();
        const int bGl = rbase >> 12;            // batch for [B*S] row space
        const int s0  = rbase & (Ss - 1);
        #pragma unroll
        for (int i = 0; i < 8; i++) {
            const int e  = i * 256 + tid;       // 0..2047
            const int c  = e >> 4;
            const int ru = e & 15;
            uint4 hv = *(const uint4*)(sTh + c * 136 + ru * 8);
            uint4 lv = *(const uint4*)(sTl + c * 136 + ru * 8);
            size_t gi;
            if (EPI == E_KVP)
                gi = ((size_t)bz * Dd + cbase + c) * (size_t)Dd + rbase + ru * 8;
            else
                gi = ((size_t)bGl * Dd + cbase + c) * (size_t)Ss + s0 + ru * 8;
            *(uint4*)(Ch + gi) = hv;
            *(uint4*)(Cl + gi) = lv;
        }
    }
}

// ---------------------------------------------------------------------------
// Pre-split fp32 -> (hi, lo) bf16
// ---------------------------------------------------------------------------
__global__ void presplit_k(const float* __restrict__ x,
                           __nv_bfloat16* __restrict__ h, __nv_bfloat16* __restrict__ l)
{
    const size_t i = ((size_t)blockIdx.x * 256 + threadIdx.x) * 4;
    float4 v = *(const float4*)(x + i);
    __nv_bfloat16 h0, l0, h1, l1, h2, l2, h3, l3;
    split_bf16(v.x, h0, l0); split_bf16(v.y, h1, l1);
    split_bf16(v.z, h2, l2); split_bf16(v.w, h3, l3);
    *(uint2*)(h + i) = make_uint2(pack2(h0, h1), pack2(h2, h3));
    *(uint2*)(l + i) = make_uint2(pack2(l0, l1), pack2(l2, l3));
}

// ---------------------------------------------------------------------------
// W [K,N] -> Wt [N,K] split (smem tile transpose)
// ---------------------------------------------------------------------------
__global__ void wsplit_k(const float* __restrict__ Wq, const float* __restrict__ Wk,
                         const float* __restrict__ Wv, const float* __restrict__ Wo)
{
    __shared__ float t[32][33];
    const float* W = (blockIdx.z == 0) ? Wq : (blockIdx.z == 1) ? Wk
                   : (blockIdx.z == 2) ? Wv : Wo;
    __nv_bfloat16* Th = g_WtH + (size_t)blockIdx.z * Dd * Dd;
    __nv_bfloat16* Tl = g_WtL + (size_t)blockIdx.z * Dd * Dd;
    const int n0 = blockIdx.x * 32, k0 = blockIdx.y * 32;
    const int tx = threadIdx.x, ty = threadIdx.y;
    #pragma unroll
    for (int i = 0; i < 4; i++)
        t[ty + i * 8][tx] = W[(size_t)(k0 + ty + i * 8) * Dd + n0 + tx];
    __syncthreads();
    #pragma unroll
    for (int i = 0; i < 4; i++) {
        const int r = ty + i * 8;
        __nv_bfloat16 h, l;
        split_bf16(t[tx][r], h, l);
        const size_t idx = (size_t)(n0 + r) * Dd + k0 + tx;
        Th[idx] = h;
        Tl[idx] = l;
    }
}

// ---------------------------------------------------------------------------
// k_sum[b,d] = sum_s k_phi^T[b,d,s]  (one warp per contiguous row)
// ---------------------------------------------------------------------------
__global__ void ksum_k()
{
    const int gw = (blockIdx.x * blockDim.x + threadIdx.x) >> 5;  // 0..4095
    const int lane = threadIdx.x & 31;
    const uint4* ph = (const uint4*)(g_kTh + (size_t)gw * Ss);
    const uint4* pl = (const uint4*)(g_kTl + (size_t)gw * Ss);
    float s = 0.f;
    #pragma unroll 4
    for (int i = 0; i < 16; i++) {
        const int u = i * 32 + lane;
        uint4 xh = ph[u], xl = pl[u];
        const __nv_bfloat162* h2 = (const __nv_bfloat162*)&xh;
        const __nv_bfloat162* l2 = (const __nv_bfloat162*)&xl;
        #pragma unroll
        for (int t = 0; t < 4; t++) {
            float2 fh = __bfloat1622float2(h2[t]);
            float2 fl = __bfloat1622float2(l2[t]);
            s += (fh.x + fl.x) + (fh.y + fl.y);
        }
    }
    #pragma unroll
    for (int o = 16; o; o >>= 1) s += __shfl_xor_sync(0xffffffffu, s, o);
    if (lane == 0) g_ksum[gw] = s;
}

// ---------------------------------------------------------------------------
// z[b,s] = 1 / (dot(q_phi[b,s,:], k_sum[b,:]) + 1e-6)
// ---------------------------------------------------------------------------
__global__ void z_k()
{
    const int gw = (blockIdx.x * blockDim.x + threadIdx.x) >> 5;  // 0..16383
    const int lane = threadIdx.x & 31;
    const int b = gw >> 12;
    const uint4* qh4 = (const uint4*)(g_qh + (size_t)gw * Dd);
    const uint4* ql4 = (const uint4*)(g_ql + (size_t)gw * Dd);
    const float4* ks4 = (const float4*)(g_ksum + b * Dd);
    float s = 0.f;
    #pragma unroll
    for (int i = 0; i < 4; i++) {
        const int u = i * 32 + lane;
        uint4 xh = qh4[u], xl = ql4[u];
        float4 k0 = ks4[u * 2], k1 = ks4[u * 2 + 1];
        const __nv_bfloat162* h2 = (const __nv_bfloat162*)&xh;
        const __nv_bfloat162* l2 = (const __nv_bfloat162*)&xl;
        const float* kf = (const float*)&k0;
        #pragma unroll
        for (int t = 0; t < 2; t++) {
            float2 fh = __bfloat1622float2(h2[t]);
            float2 fl = __bfloat1622float2(l2[t]);
            s += (fh.x + fl.x) * kf[t * 2] + (fh.y + fl.y) * kf[t * 2 + 1];
        }
        const float* kg = (const float*)&k1;
        #pragma unroll
        for (int t = 0; t < 2; t++) {
            float2 fh = __bfloat1622float2(h2[2 + t]);
            float2 fl = __bfloat1622float2(l2[2 + t]);
            s += (fh.x + fl.x) * kg[t * 2] + (fh.y + fl.y) * kg[t * 2 + 1];
        }
    }
    #pragma unroll
    for (int o = 16; o; o >>= 1) s += __shfl_xor_sync(0xffffffffu, s, o);
    if (lane == 0) g_z[gw] = 1.0f / (s + 1e-6f);
}

// ---------------------------------------------------------------------------
// Launch
// ---------------------------------------------------------------------------
extern "C" void kernel_launch(void* const* d_in, const int* in_sizes, int n_in,
                              void* d_out, int out_size)
{
    (void)in_sizes; (void)n_in; (void)out_size;
    const float* inputs  = (const float*)d_in[0];
    const float* context = (const float*)d_in[1];
    const float* Wq = (const float*)d_in[2];
    const float* bq = (const float*)d_in[3];
    const float* Wk = (const float*)d_in[4];
    const float* bk = (const float*)d_in[5];
    const float* Wv = (const float*)d_in[6];
    const float* bv = (const float*)d_in[7];
    const float* Wo = (const float*)d_in[8];
    const float* bo = (const float*)d_in[9];
    float* out = (float*)d_out;

    __nv_bfloat16 *ih, *il, *ch, *cl, *qh, *ql, *kTh, *kTl, *vTh, *vTl,
                  *ath, *atl, *kvh, *kvl, *WtH, *WtL;
    float *zp;
    cudaGetSymbolAddress((void**)&ih,  g_ih);  cudaGetSymbolAddress((void**)&il,  g_il);
    cudaGetSymbolAddress((void**)&ch,  g_ch);  cudaGetSymbolAddress((void**)&cl,  g_cl);
    cudaGetSymbolAddress((void**)&qh,  g_qh);  cudaGetSymbolAddress((void**)&ql,  g_ql);
    cudaGetSymbolAddress((void**)&kTh, g_kTh); cudaGetSymbolAddress((void**)&kTl, g_kTl);
    cudaGetSymbolAddress((void**)&vTh, g_vTh); cudaGetSymbolAddress((void**)&vTl, g_vTl);
    cudaGetSymbolAddress((void**)&ath, g_ath); cudaGetSymbolAddress((void**)&atl, g_atl);
    cudaGetSymbolAddress((void**)&kvh, g_kvh); cudaGetSymbolAddress((void**)&kvl, g_kvl);
    cudaGetSymbolAddress((void**)&WtH, g_WtH); cudaGetSymbolAddress((void**)&WtL, g_WtL);
    cudaGetSymbolAddress((void**)&zp,  g_z);

    cudaFuncSetAttribute(mma_gemm<E_Q>,   cudaFuncAttributeMaxDynamicSharedMemorySize, SMEM_DYN);
    cudaFuncSetAttribute(mma_gemm<E_K>,   cudaFuncAttributeMaxDynamicSharedMemorySize, SMEM_DYN);
    cudaFuncSetAttribute(mma_gemm<E_V>,   cudaFuncAttributeMaxDynamicSharedMemorySize, SMEM_DYN);
    cudaFuncSetAttribute(mma_gemm<E_KVP>, cudaFuncAttributeMaxDynamicSharedMemorySize, SMEM_DYN);
    cudaFuncSetAttribute(mma_gemm<E_ATT>, cudaFuncAttributeMaxDynamicSharedMemorySize, SMEM_DYN);
    cudaFuncSetAttribute(mma_gemm<E_OUT>, cudaFuncAttributeMaxDynamicSharedMemorySize, SMEM_DYN);

    const size_t DD2 = (size_t)Dd * Dd;
    const dim3 blk(256);

    // 0. Pre-split weights (transposed) and activations
    wsplit_k<<<dim3(32, 32, 4), dim3(32, 8)>>>(Wq, Wk, Wv, Wo);
    presplit_k<<<16384, 256>>>(inputs,  ih, il);
    presplit_k<<<16384, 256>>>(context, ch, cl);

    // 1-3. Projections
    mma_gemm<E_Q><<<dim3(8, 128, 1), blk, SMEM_DYN>>>(
        ih, il, WtH, WtL, Dd, Dd, Dd, 0, 0, bq, nullptr, nullptr, nullptr, qh, ql);
    mma_gemm<E_K><<<dim3(8, 128, 1), blk, SMEM_DYN>>>(
        ch, cl, WtH + DD2, WtL + DD2, Dd, Dd, Dd, 0, 0, bk, nullptr, nullptr, nullptr, kTh, kTl);
    mma_gemm<E_V><<<dim3(8, 128, 1), blk, SMEM_DYN>>>(
        ch, cl, WtH + 2 * DD2, WtL + 2 * DD2, Dd, Dd, Dd, 0, 0, bv, nullptr, nullptr, nullptr, vTh, vTl);

    // 4-5. k_sum, z
    ksum_k<<<512, 256>>>();
    z_k<<<2048, 256>>>();

    // 6. kv^T[b,e,d] = (k^T @ v)^T   (M=d rows, N=e cols, K=s)
    mma_gemm<E_KVP><<<dim3(8, 8, 4), blk, SMEM_DYN>>>(
        kTh, kTl, vTh, vTl, Ss, Ss, Ss,
        (long long)Dd * Ss, (long long)Dd * Ss,
        nullptr, nullptr, nullptr, nullptr, kvh, kvl);

    // 7. att[b,s,e] = (q_phi @ kv) * z
    mma_gemm<E_ATT><<<dim3(8, 32, 4), blk, SMEM_DYN>>>(
        qh, ql, kvh, kvl, Dd, Dd, Dd,
        (long long)Ss * Dd, (long long)Dd * Dd,
        nullptr, zp, nullptr, nullptr, ath, atl);

    // 8. out = att @ Wo + bo + inputs
    mma_gemm<E_OUT><<<dim3(8, 128, 1), blk, SMEM_DYN>>>(
        ath, atl, WtH + 3 * DD2, WtL + 3 * DD2, Dd, Dd, Dd, 0, 0,
        bo, nullptr, inputs, out, nullptr, nullptr);
}

// round 5
// speedup vs baseline: 6.5372x; 2.6482x over previous
#include <cuda_runtime.h>
#include <cuda_fp16.h>
#include <stdint.h>

#define Bb 4
#define Ss 4096
#define Dd 1024
#define MTOT (Bb * Ss)   // 16384

// ---------------------------------------------------------------------------
// Scratch (device globals; allocation is forbidden)
// ---------------------------------------------------------------------------
__device__ __half g_i16 [(size_t)MTOT * Dd];        // inputs fp16
__device__ __half g_c16 [(size_t)MTOT * Dd];        // context fp16
__device__ __half g_q16 [(size_t)MTOT * Dd];        // q_phi fp16
__device__ __half g_kT16[(size_t)Bb * Dd * Ss];     // k_phi^T [b,d,s]
__device__ __half g_vT16[(size_t)Bb * Dd * Ss];     // v^T     [b,e,s]
__device__ __half g_at16[(size_t)MTOT * Dd];        // att * 1024
__device__ __half g_kvT16[(size_t)Bb * Dd * Dd];    // kv^T    [b,e,d]
__device__ __half g_Wt16[(size_t)4 * Dd * Dd];      // W^T (q,k,v,o)
__device__ float  g_ksum[Bb * Dd];
__device__ float  g_z  [Bb * Ss];

#define ATT_SCALE    1024.0f
#define ATT_INVSCALE (1.0f / 1024.0f)

// ---------------------------------------------------------------------------
// Helpers (baseline compute_103: mma.sync / ldmatrix / cp.async only)
// ---------------------------------------------------------------------------
static __device__ __forceinline__ uint32_t smem_u32(const void* p) {
    uint32_t a;
    asm("{ .reg .u64 t; cvta.to.shared.u64 t, %1; cvt.u32.u64 %0, t; }"
        : "=r"(a) : "l"(p));
    return a;
}

static __device__ __forceinline__ void ldsm4(uint32_t* r, uint32_t addr) {
    asm volatile("ldmatrix.sync.aligned.m8n8.x4.shared.b16 {%0,%1,%2,%3}, [%4];"
                 : "=r"(r[0]), "=r"(r[1]), "=r"(r[2]), "=r"(r[3]) : "r"(addr));
}

static __device__ __forceinline__ void mma16816(float* d, const uint32_t* a,
                                                const uint32_t* b) {
    asm volatile(
        "mma.sync.aligned.m16n8k16.row.col.f32.f16.f16.f32 "
        "{%0,%1,%2,%3}, {%4,%5,%6,%7}, {%8,%9}, {%0,%1,%2,%3};"
        : "+f"(d[0]), "+f"(d[1]), "+f"(d[2]), "+f"(d[3])
        : "r"(a[0]), "r"(a[1]), "r"(a[2]), "r"(a[3]), "r"(b[0]), "r"(b[1]));
}

#define CP16(dst, src) \
    asm volatile("cp.async.cg.shared.global [%0], [%1], 16;" :: "r"(dst), "l"(src))
#define CP_COMMIT() asm volatile("cp.async.commit_group;" ::: "memory")
#define CP_WAIT1()  asm volatile("cp.async.wait_group 1;" ::: "memory")

static __device__ __forceinline__ uint32_t pack2h(__half a, __half b) {
    return (uint32_t)__half_as_ushort(a) | ((uint32_t)__half_as_ushort(b) << 16);
}

// ---------------------------------------------------------------------------
// fp16 warp-MMA GEMM: C[128x128] = A @ B^T  (fp32 accumulate)
//   A: [M,K] K-major fp16; B: [N,K] K-major fp16.
//   CTA 128x128, K-chunk 64, 8 warps (4M x 2N), warp tile 32x64.
//   3-stage cp.async pipeline (32KB/stage), xor-swizzled 128B rows.
//   2 CTAs/SM target.
// ---------------------------------------------------------------------------
enum { E_Q = 0, E_K = 1, E_V = 2, E_KVP = 3, E_ATT = 4, E_OUT = 5 };

#define TILE_B   16384            // 128 rows x 128B (128x64 fp16)
#define STAGE_B  (2 * TILE_B)     // A | B
#define SMEM_DYN (3 * STAGE_B)    // 98304

template<int EPI>
__global__ __launch_bounds__(256, 2)
void mma_gemm(const __half* __restrict__ Ag, const __half* __restrict__ Bg,
              int K, int lda, int ldb, long long sA, long long sB,
              const float* __restrict__ bias, const float* __restrict__ zarr,
              const float* __restrict__ resid, float* __restrict__ Cf,
              __half* __restrict__ Ch)
{
    extern __shared__ __align__(1024) char dsm[];
    const uint32_t sbase = smem_u32(dsm);

    const int tid  = threadIdx.x;
    const int w    = tid >> 5, lane = tid & 31;
    const int wm0  = (w >> 1) * 32;     // warp M offset
    const int wn0  = (w & 1) * 64;      // warp N offset
    const int bz    = blockIdx.z;
    const int rbase = blockIdx.y * 128;
    const int cbase = blockIdx.x * 128;

    const __half* pA = Ag + (size_t)bz * sA;
    const __half* pB = Bg + (size_t)bz * sB;

    float acc[2][8][4];
    #pragma unroll
    for (int a = 0; a < 2; a++)
        #pragma unroll
        for (int b = 0; b < 8; b++)
            #pragma unroll
            for (int c = 0; c < 4; c++) acc[a][b][c] = 0.f;

    // ---- stage loader: 2 tiles of 128 rows x 128B, xor-8 swizzle ----
    auto load_stage = [&](int stg, int it) {
        const uint32_t sb = sbase + stg * STAGE_B;
        const size_t k0 = (size_t)it * 64;
        #pragma unroll
        for (int i = 0; i < 4; i++) {
            const int row = (tid >> 3) + i * 32;
            const int u   = tid & 7;
            const uint32_t off = ((uint32_t)row << 7) + (uint32_t)((u ^ (row & 7)) << 4);
            const size_t ea = (size_t)(rbase + row) * lda + k0 + (size_t)u * 8;
            const size_t eb = (size_t)(cbase + row) * ldb + k0 + (size_t)u * 8;
            CP16(sb + off,          pA + ea);
            CP16(sb + TILE_B + off, pB + eb);
        }
    };

    const int nch = K >> 6;
    load_stage(0, 0); CP_COMMIT();
    load_stage(1, 1); CP_COMMIT();

    const int la15 = lane & 15, la7 = lane & 7;
    const uint32_t aRowB = (uint32_t)(wm0 + la15) << 7;
    const int aSel = lane >> 4;
    const int bRow = wn0 + la7 + ((lane >> 1) & 8);
    const int bSel = (lane >> 3) & 1;

    for (int it = 0; it < nch; ++it) {
        CP_WAIT1();
        __syncthreads();
        if (it + 2 < nch) load_stage((it + 2) % 3, it + 2);
        CP_COMMIT();

        const uint32_t sb = sbase + (it % 3) * STAGE_B;
        #pragma unroll
        for (int ks = 0; ks < 4; ++ks) {
            uint32_t ah[2][4], bh[4][4];
            #pragma unroll
            for (int mt = 0; mt < 2; mt++) {
                const uint32_t ad = sb + aRowB + (mt << 11)
                                  + (uint32_t)((((ks << 1) + aSel) ^ la7) << 4);
                ldsm4(ah[mt], ad);
            }
            #pragma unroll
            for (int nt = 0; nt < 4; nt++) {
                const uint32_t bd = sb + TILE_B
                                  + ((uint32_t)(bRow + (nt << 4)) << 7)
                                  + (uint32_t)((((ks << 1) + bSel) ^ la7) << 4);
                ldsm4(bh[nt], bd);
            }
            #pragma unroll
            for (int mt = 0; mt < 2; mt++)
                #pragma unroll
                for (int nt = 0; nt < 4; nt++)
                    #pragma unroll
                    for (int s2 = 0; s2 < 2; s2++)
                        mma16816(acc[mt][nt * 2 + s2], ah[mt], &bh[nt][s2 * 2]);
        }
    }

    // ------------------------------ epilogue -------------------------------
    const int rQ = lane >> 2;          // 0..7
    const int cP = (lane & 3) * 2;     // 0,2,4,6

    if (EPI == E_Q || EPI == E_ATT || EPI == E_OUT) {
        #pragma unroll
        for (int mt = 0; mt < 2; mt++)
            #pragma unroll
            for (int h = 0; h < 2; h++) {
                const int grow = rbase + wm0 + mt * 16 + rQ + h * 8;
                float zv = 1.f;
                if (EPI == E_ATT) zv = zarr[(size_t)bz * Ss + grow] * ATT_SCALE;
                #pragma unroll
                for (int nt8 = 0; nt8 < 8; nt8++) {
                    const int gcol = cbase + wn0 + nt8 * 8 + cP;
                    float v0 = acc[mt][nt8][h * 2 + 0];
                    float v1 = acc[mt][nt8][h * 2 + 1];
                    if (EPI == E_OUT) { v0 *= ATT_INVSCALE; v1 *= ATT_INVSCALE; }
                    if (EPI == E_Q || EPI == E_OUT) {
                        v0 += bias[gcol];
                        v1 += bias[gcol + 1];
                    }
                    if (EPI == E_Q) {
                        v0 = (v0 > 0.f) ? (v0 + 1.f) : __expf(v0);
                        v1 = (v1 > 0.f) ? (v1 + 1.f) : __expf(v1);
                    }
                    if (EPI == E_ATT) { v0 *= zv; v1 *= zv; }
                    if (EPI == E_OUT) {
                        const size_t gi = (size_t)grow * Dd + gcol;
                        float2 rv = *(const float2*)(resid + gi);
                        *(float2*)(Cf + gi) = make_float2(v0 + rv.x, v1 + rv.y);
                    } else {
                        const size_t gi = (EPI == E_Q)
                            ? (size_t)grow * Dd + gcol
                            : ((size_t)bz * Ss + grow) * (size_t)Dd + gcol;
                        *(uint32_t*)(Ch + gi) =
                            pack2h(__float2half_rn(v0), __float2half_rn(v1));
                    }
                }
            }
    } else {
        // E_K / E_V / E_KVP: transpose via smem staging, coalesced stores
        __syncthreads();                      // compute done; reuse dsm
        __half* sT = (__half*)dsm;            // 128 cols x 136 rows fp16
        #pragma unroll
        for (int mt = 0; mt < 2; mt++)
            #pragma unroll
            for (int h = 0; h < 2; h++) {
                const int r = wm0 + mt * 16 + rQ + h * 8;
                #pragma unroll
                for (int nt8 = 0; nt8 < 8; nt8++) {
                    const int c = wn0 + nt8 * 8 + cP;
                    float v0 = acc[mt][nt8][h * 2 + 0];
                    float v1 = acc[mt][nt8][h * 2 + 1];
                    if (EPI == E_K || EPI == E_V) {
                        v0 += bias[cbase + c];
                        v1 += bias[cbase + c + 1];
                    }
                    if (EPI == E_K) {
                        v0 = (v0 > 0.f) ? (v0 + 1.f) : __expf(v0);
                        v1 = (v1 > 0.f) ? (v1 + 1.f) : __expf(v1);
                    }
                    sT[c * 136 + r]       = __float2half_rn(v0);
                    sT[(c + 1) * 136 + r] = __float2half_rn(v1);
                }
            }
        __syncthreads();
        const int bGl = rbase >> 12;
        const int s0  = rbase & (Ss - 1);
        #pragma unroll
        for (int i = 0; i < 8; i++) {
            const int e  = i * 256 + tid;       // 0..2047
            const int c  = e >> 4;
            const int ru = e & 15;
            uint4 hv = *(const uint4*)(sT + c * 136 + ru * 8);
            size_t gi;
            if (EPI == E_KVP)
                gi = ((size_t)bz * Dd + cbase + c) * (size_t)Dd + rbase + ru * 8;
            else
                gi = ((size_t)bGl * Dd + cbase + c) * (size_t)Ss + s0 + ru * 8;
            *(uint4*)(Ch + gi) = hv;
        }
    }
}

// ---------------------------------------------------------------------------
// fp32 -> fp16 convert (8 elems/thread)
// ---------------------------------------------------------------------------
__global__ void tofp16_k(const float* __restrict__ x, __half* __restrict__ h)
{
    const size_t i = ((size_t)blockIdx.x * 256 + threadIdx.x) * 8;
    float4 a = *(const float4*)(x + i);
    float4 b = *(const float4*)(x + i + 4);
    uint4 o;
    o.x = pack2h(__float2half_rn(a.x), __float2half_rn(a.y));
    o.y = pack2h(__float2half_rn(a.z), __float2half_rn(a.w));
    o.z = pack2h(__float2half_rn(b.x), __float2half_rn(b.y));
    o.w = pack2h(__float2half_rn(b.z), __float2half_rn(b.w));
    *(uint4*)(h + i) = o;
}

// ---------------------------------------------------------------------------
// W [K,N] -> Wt [N,K] fp16 (smem tile transpose)
// ---------------------------------------------------------------------------
__global__ void wsplit_k(const float* __restrict__ Wq, const float* __restrict__ Wk,
                         const float* __restrict__ Wv, const float* __restrict__ Wo)
{
    __shared__ float t[32][33];
    const float* W = (blockIdx.z == 0) ? Wq : (blockIdx.z == 1) ? Wk
                   : (blockIdx.z == 2) ? Wv : Wo;
    __half* Th = g_Wt16 + (size_t)blockIdx.z * Dd * Dd;
    const int n0 = blockIdx.x * 32, k0 = blockIdx.y * 32;
    const int tx = threadIdx.x, ty = threadIdx.y;
    #pragma unroll
    for (int i = 0; i < 4; i++)
        t[ty + i * 8][tx] = W[(size_t)(k0 + ty + i * 8) * Dd + n0 + tx];
    __syncthreads();
    #pragma unroll
    for (int i = 0; i < 4; i++) {
        const int r = ty + i * 8;
        Th[(size_t)(n0 + r) * Dd + k0 + tx] = __float2half_rn(t[tx][r]);
    }
}

// ---------------------------------------------------------------------------
// k_sum[b,d] = sum_s k_phi^T[b,d,s]  (one warp per contiguous row)
// ---------------------------------------------------------------------------
__global__ void ksum_k()
{
    const int gw = (blockIdx.x * blockDim.x + threadIdx.x) >> 5;  // 0..4095
    const int lane = threadIdx.x & 31;
    const uint4* ph = (const uint4*)(g_kT16 + (size_t)gw * Ss);
    float s = 0.f;
    #pragma unroll 4
    for (int i = 0; i < 16; i++) {
        uint4 xh = ph[i * 32 + lane];
        const __half2* h2 = (const __half2*)&xh;
        #pragma unroll
        for (int t = 0; t < 4; t++) {
            float2 f = __half22float2(h2[t]);
            s += f.x + f.y;
        }
    }
    #pragma unroll
    for (int o = 16; o; o >>= 1) s += __shfl_xor_sync(0xffffffffu, s, o);
    if (lane == 0) g_ksum[gw] = s;
}

// ---------------------------------------------------------------------------
// z[b,s] = 1 / (dot(q_phi[b,s,:], k_sum[b,:]) + 1e-6)
// ---------------------------------------------------------------------------
__global__ void z_k()
{
    const int gw = (blockIdx.x * blockDim.x + threadIdx.x) >> 5;  // 0..16383
    const int lane = threadIdx.x & 31;
    const int b = gw >> 12;
    const uint4* q4 = (const uint4*)(g_q16 + (size_t)gw * Dd);
    const float4* ks4 = (const float4*)(g_ksum + b * Dd);
    float s = 0.f;
    #pragma unroll
    for (int i = 0; i < 4; i++) {
        const int u = i * 32 + lane;
        uint4 xq = q4[u];
        float4 k0 = ks4[u * 2], k1 = ks4[u * 2 + 1];
        const __half2* h2 = (const __half2*)&xq;
        const float* kf = (const float*)&k0;
        #pragma unroll
        for (int t = 0; t < 2; t++) {
            float2 f = __half22float2(h2[t]);
            s += f.x * kf[t * 2] + f.y * kf[t * 2 + 1];
        }
        const float* kg = (const float*)&k1;
        #pragma unroll
        for (int t = 0; t < 2; t++) {
            float2 f = __half22float2(h2[2 + t]);
            s += f.x * kg[t * 2] + f.y * kg[t * 2 + 1];
        }
    }
    #pragma unroll
    for (int o = 16; o; o >>= 1) s += __shfl_xor_sync(0xffffffffu, s, o);
    if (lane == 0) g_z[gw] = 1.0f / (s + 1e-6f);
}

// ---------------------------------------------------------------------------
// Launch
// ---------------------------------------------------------------------------
extern "C" void kernel_launch(void* const* d_in, const int* in_sizes, int n_in,
                              void* d_out, int out_size)
{
    (void)in_sizes; (void)n_in; (void)out_size;
    const float* inputs  = (const float*)d_in[0];
    const float* context = (const float*)d_in[1];
    const float* Wq = (const float*)d_in[2];
    const float* bq = (const float*)d_in[3];
    const float* Wk = (const float*)d_in[4];
    const float* bk = (const float*)d_in[5];
    const float* Wv = (const float*)d_in[6];
    const float* bv = (const float*)d_in[7];
    const float* Wo = (const float*)d_in[8];
    const float* bo = (const float*)d_in[9];
    float* out = (float*)d_out;

    __half *i16, *c16, *q16, *kT, *vT, *at, *kvT, *Wt;
    float *zp;
    cudaGetSymbolAddress((void**)&i16, g_i16);
    cudaGetSymbolAddress((void**)&c16, g_c16);
    cudaGetSymbolAddress((void**)&q16, g_q16);
    cudaGetSymbolAddress((void**)&kT,  g_kT16);
    cudaGetSymbolAddress((void**)&vT,  g_vT16);
    cudaGetSymbolAddress((void**)&at,  g_at16);
    cudaGetSymbolAddress((void**)&kvT, g_kvT16);
    cudaGetSymbolAddress((void**)&Wt,  g_Wt16);
    cudaGetSymbolAddress((void**)&zp,  g_z);

    cudaFuncSetAttribute(mma_gemm<E_Q>,   cudaFuncAttributeMaxDynamicSharedMemorySize, SMEM_DYN);
    cudaFuncSetAttribute(mma_gemm<E_K>,   cudaFuncAttributeMaxDynamicSharedMemorySize, SMEM_DYN);
    cudaFuncSetAttribute(mma_gemm<E_V>,   cudaFuncAttributeMaxDynamicSharedMemorySize, SMEM_DYN);
    cudaFuncSetAttribute(mma_gemm<E_KVP>, cudaFuncAttributeMaxDynamicSharedMemorySize, SMEM_DYN);
    cudaFuncSetAttribute(mma_gemm<E_ATT>, cudaFuncAttributeMaxDynamicSharedMemorySize, SMEM_DYN);
    cudaFuncSetAttribute(mma_gemm<E_OUT>, cudaFuncAttributeMaxDynamicSharedMemorySize, SMEM_DYN);

    const size_t DD2 = (size_t)Dd * Dd;
    const dim3 blk(256);

    // 0. Convert weights (transposed) and activations to fp16
    wsplit_k<<<dim3(32, 32, 4), dim3(32, 8)>>>(Wq, Wk, Wv, Wo);
    tofp16_k<<<8192, 256>>>(inputs,  i16);
    tofp16_k<<<8192, 256>>>(context, c16);

    // 1-3. Projections
    mma_gemm<E_Q><<<dim3(8, 128, 1), blk, SMEM_DYN>>>(
        i16, Wt, Dd, Dd, Dd, 0, 0, bq, nullptr, nullptr, nullptr, q16);
    mma_gemm<E_K><<<dim3(8, 128, 1), blk, SMEM_DYN>>>(
        c16, Wt + DD2, Dd, Dd, Dd, 0, 0, bk, nullptr, nullptr, nullptr, kT);
    mma_gemm<E_V><<<dim3(8, 128, 1), blk, SMEM_DYN>>>(
        c16, Wt + 2 * DD2, Dd, Dd, Dd, 0, 0, bv, nullptr, nullptr, nullptr, vT);

    // 4-5. k_sum, z
    ksum_k<<<512, 256>>>();
    z_k<<<2048, 256>>>();

    // 6. kv^T[b,e,d] = (k^T @ v)^T  (M=d rows, N=e cols, K=s)
    mma_gemm<E_KVP><<<dim3(8, 8, 4), blk, SMEM_DYN>>>(
        kT, vT, Ss, Ss, Ss,
        (long long)Dd * Ss, (long long)Dd * Ss,
        nullptr, nullptr, nullptr, nullptr, kvT);

    // 7. att[b,s,e] = (q_phi @ kv) * z * ATT_SCALE
    mma_gemm<E_ATT><<<dim3(8, 32, 4), blk, SMEM_DYN>>>(
        q16, kvT, Dd, Dd, Dd,
        (long long)Ss * Dd, (long long)Dd * Dd,
        nullptr, zp, nullptr, nullptr, at);

    // 8. out = (att_scaled @ Wo) / ATT_SCALE + bo + inputs
    mma_gemm<E_OUT><<<dim3(8, 128, 1), blk, SMEM_DYN>>>(
        at, Wt + 3 * DD2, Dd, Dd, Dd, 0, 0,
        bo, nullptr, inputs, out, nullptr);
}

// round 6
// speedup vs baseline: 6.8593x; 1.0493x over previous
#include <cuda_runtime.h>
#include <cuda_fp16.h>
#include <stdint.h>

#define Bb 4
#define Ss 4096
#define Dd 1024
#define MTOT (Bb * Ss)   // 16384

// ---------------------------------------------------------------------------
// Scratch (device globals; allocation is forbidden)
// ---------------------------------------------------------------------------
__device__ __half g_i16 [(size_t)MTOT * Dd];        // inputs fp16
__device__ __half g_c16 [(size_t)MTOT * Dd];        // context fp16
__device__ __half g_q16 [(size_t)MTOT * Dd];        // q_phi fp16
__device__ __half g_kT16[(size_t)Bb * Dd * Ss];     // k_phi^T [b,d,s]
__device__ __half g_vT16[(size_t)Bb * Dd * Ss];     // v^T     [b,e,s]
__device__ __half g_at16[(size_t)MTOT * Dd];        // att * 1024
__device__ __half g_kvT16[(size_t)Bb * Dd * Dd];    // kv^T    [b,e,d]
__device__ __half g_Wt16[(size_t)4 * Dd * Dd];      // W^T (q,k,v,o)
__device__ float  g_ksum[Bb * Dd];
__device__ float  g_z  [Bb * Ss];

#define ATT_SCALE    1024.0f
#define ATT_INVSCALE (1.0f / 1024.0f)

// ---------------------------------------------------------------------------
// Helpers (baseline compute_103: mma.sync / ldmatrix / cp.async only)
// ---------------------------------------------------------------------------
static __device__ __forceinline__ uint32_t smem_u32(const void* p) {
    uint32_t a;
    asm("{ .reg .u64 t; cvta.to.shared.u64 t, %1; cvt.u32.u64 %0, t; }"
        : "=r"(a) : "l"(p));
    return a;
}

static __device__ __forceinline__ void ldsm4(uint32_t* r, uint32_t addr) {
    asm volatile("ldmatrix.sync.aligned.m8n8.x4.shared.b16 {%0,%1,%2,%3}, [%4];"
                 : "=r"(r[0]), "=r"(r[1]), "=r"(r[2]), "=r"(r[3]) : "r"(addr));
}

static __device__ __forceinline__ void mma16816(float* d, const uint32_t* a,
                                                const uint32_t* b) {
    asm volatile(
        "mma.sync.aligned.m16n8k16.row.col.f32.f16.f16.f32 "
        "{%0,%1,%2,%3}, {%4,%5,%6,%7}, {%8,%9}, {%0,%1,%2,%3};"
        : "+f"(d[0]), "+f"(d[1]), "+f"(d[2]), "+f"(d[3])
        : "r"(a[0]), "r"(a[1]), "r"(a[2]), "r"(a[3]), "r"(b[0]), "r"(b[1]));
}

#define CP16(dst, src) \
    asm volatile("cp.async.cg.shared.global [%0], [%1], 16;" :: "r"(dst), "l"(src))
#define CP_COMMIT() asm volatile("cp.async.commit_group;" ::: "memory")
#define CP_WAIT1()  asm volatile("cp.async.wait_group 1;" ::: "memory")

static __device__ __forceinline__ uint32_t pack2h(__half a, __half b) {
    return (uint32_t)__half_as_ushort(a) | ((uint32_t)__half_as_ushort(b) << 16);
}

// ---------------------------------------------------------------------------
// fp16 warp-MMA GEMM: C[128x128] = A @ B^T  (fp32 accumulate)
//   A: [M,K] K-major fp16; B: [N,K] K-major fp16.
//   CTA 128x128, K-chunk 64, 4 warps (2M x 2N), warp tile 64x64.
//   3-stage cp.async pipeline (32KB/stage), xor-swizzled 128B rows.
//   128 threads/CTA, 2 CTAs/SM.
// ---------------------------------------------------------------------------
enum { E_Q = 0, E_K = 1, E_V = 2, E_KVP = 3, E_ATT = 4, E_OUT = 5 };

#define TILE_B   16384            // 128 rows x 128B (128x64 fp16)
#define STAGE_B  (2 * TILE_B)     // A | B
#define SMEM_DYN (3 * STAGE_B)    // 98304

template<int EPI>
__global__ __launch_bounds__(128, 2)
void mma_gemm(const __half* __restrict__ Ag, const __half* __restrict__ Bg,
              int K, int lda, int ldb, long long sA, long long sB,
              const float* __restrict__ bias, const float* __restrict__ zarr,
              const float* __restrict__ resid, float* __restrict__ Cf,
              __half* __restrict__ Ch)
{
    extern __shared__ __align__(1024) char dsm[];
    const uint32_t sbase = smem_u32(dsm);

    const int tid  = threadIdx.x;
    const int w    = tid >> 5, lane = tid & 31;
    const int wm0  = (w >> 1) * 64;     // warp M offset (2x2 warps of 64x64)
    const int wn0  = (w & 1) * 64;      // warp N offset
    const int bz    = blockIdx.z;
    const int rbase = blockIdx.y * 128;
    const int cbase = blockIdx.x * 128;

    const __half* pA = Ag + (size_t)bz * sA;
    const __half* pB = Bg + (size_t)bz * sB;

    float acc[4][8][4];
    #pragma unroll
    for (int a = 0; a < 4; a++)
        #pragma unroll
        for (int b = 0; b < 8; b++)
            #pragma unroll
            for (int c = 0; c < 4; c++) acc[a][b][c] = 0.f;

    // ---- stage loader: 2 tiles of 128 rows x 128B, xor-8 swizzle, 128 thr ----
    auto load_stage = [&](int stg, int it) {
        const uint32_t sb = sbase + stg * STAGE_B;
        const size_t k0 = (size_t)it * 64;
        #pragma unroll
        for (int i = 0; i < 8; i++) {
            const int row = (tid >> 3) + i * 16;
            const int u   = tid & 7;
            const uint32_t off = ((uint32_t)row << 7) + (uint32_t)((u ^ (row & 7)) << 4);
            const size_t ea = (size_t)(rbase + row) * lda + k0 + (size_t)u * 8;
            const size_t eb = (size_t)(cbase + row) * ldb + k0 + (size_t)u * 8;
            CP16(sb + off,          pA + ea);
            CP16(sb + TILE_B + off, pB + eb);
        }
    };

    const int nch = K >> 6;
    load_stage(0, 0); CP_COMMIT();
    load_stage(1, 1); CP_COMMIT();

    const int la15 = lane & 15, la7 = lane & 7;
    const uint32_t aRowB = (uint32_t)(wm0 + la15) << 7;
    const int aSel = lane >> 4;
    const int bRow = wn0 + la7 + ((lane >> 1) & 8);
    const int bSel = (lane >> 3) & 1;

    for (int it = 0; it < nch; ++it) {
        CP_WAIT1();
        __syncthreads();
        if (it + 2 < nch) load_stage((it + 2) % 3, it + 2);
        CP_COMMIT();

        const uint32_t sb = sbase + (it % 3) * STAGE_B;
        #pragma unroll
        for (int ks = 0; ks < 4; ++ks) {
            uint32_t ah[4][4], bh[4][4];
            #pragma unroll
            for (int mt = 0; mt < 4; mt++) {
                const uint32_t ad = sb + aRowB + (mt << 11)
                                  + (uint32_t)((((ks << 1) + aSel) ^ la7) << 4);
                ldsm4(ah[mt], ad);
            }
            #pragma unroll
            for (int nt = 0; nt < 4; nt++) {
                const uint32_t bd = sb + TILE_B
                                  + ((uint32_t)(bRow + (nt << 4)) << 7)
                                  + (uint32_t)((((ks << 1) + bSel) ^ la7) << 4);
                ldsm4(bh[nt], bd);
            }
            #pragma unroll
            for (int mt = 0; mt < 4; mt++)
                #pragma unroll
                for (int nt = 0; nt < 4; nt++)
                    #pragma unroll
                    for (int s2 = 0; s2 < 2; s2++)
                        mma16816(acc[mt][nt * 2 + s2], ah[mt], &bh[nt][s2 * 2]);
        }
    }

    // ------------------------------ epilogue -------------------------------
    const int rQ = lane >> 2;          // 0..7
    const int cP = (lane & 3) * 2;     // 0,2,4,6

    if (EPI == E_Q || EPI == E_ATT || EPI == E_OUT) {
        #pragma unroll
        for (int mt = 0; mt < 4; mt++)
            #pragma unroll
            for (int h = 0; h < 2; h++) {
                const int grow = rbase + wm0 + mt * 16 + rQ + h * 8;
                float zv = 1.f;
                if (EPI == E_ATT) zv = zarr[(size_t)bz * Ss + grow] * ATT_SCALE;
                #pragma unroll
                for (int nt8 = 0; nt8 < 8; nt8++) {
                    const int gcol = cbase + wn0 + nt8 * 8 + cP;
                    float v0 = acc[mt][nt8][h * 2 + 0];
                    float v1 = acc[mt][nt8][h * 2 + 1];
                    if (EPI == E_OUT) { v0 *= ATT_INVSCALE; v1 *= ATT_INVSCALE; }
                    if (EPI == E_Q || EPI == E_OUT) {
                        v0 += bias[gcol];
                        v1 += bias[gcol + 1];
                    }
                    if (EPI == E_Q) {
                        v0 = (v0 > 0.f) ? (v0 + 1.f) : __expf(v0);
                        v1 = (v1 > 0.f) ? (v1 + 1.f) : __expf(v1);
                    }
                    if (EPI == E_ATT) { v0 *= zv; v1 *= zv; }
                    if (EPI == E_OUT) {
                        const size_t gi = (size_t)grow * Dd + gcol;
                        float2 rv = *(const float2*)(resid + gi);
                        *(float2*)(Cf + gi) = make_float2(v0 + rv.x, v1 + rv.y);
                    } else {
                        const size_t gi = (EPI == E_Q)
                            ? (size_t)grow * Dd + gcol
                            : ((size_t)bz * Ss + grow) * (size_t)Dd + gcol;
                        *(uint32_t*)(Ch + gi) =
                            pack2h(__float2half_rn(v0), __float2half_rn(v1));
                    }
                }
            }
    } else {
        // E_K / E_V / E_KVP: transpose via smem staging, coalesced stores
        __syncthreads();                      // compute done; reuse dsm
        __half* sT = (__half*)dsm;            // 128 cols x 136 rows fp16
        #pragma unroll
        for (int mt = 0; mt < 4; mt++)
            #pragma unroll
            for (int h = 0; h < 2; h++) {
                const int r = wm0 + mt * 16 + rQ + h * 8;
                #pragma unroll
                for (int nt8 = 0; nt8 < 8; nt8++) {
                    const int c = wn0 + nt8 * 8 + cP;
                    float v0 = acc[mt][nt8][h * 2 + 0];
                    float v1 = acc[mt][nt8][h * 2 + 1];
                    if (EPI == E_K || EPI == E_V) {
                        v0 += bias[cbase + c];
                        v1 += bias[cbase + c + 1];
                    }
                    if (EPI == E_K) {
                        v0 = (v0 > 0.f) ? (v0 + 1.f) : __expf(v0);
                        v1 = (v1 > 0.f) ? (v1 + 1.f) : __expf(v1);
                    }
                    sT[c * 136 + r]       = __float2half_rn(v0);
                    sT[(c + 1) * 136 + r] = __float2half_rn(v1);
                }
            }
        __syncthreads();
        const int bGl = rbase >> 12;
        const int s0  = rbase & (Ss - 1);
        #pragma unroll
        for (int i = 0; i < 16; i++) {
            const int e  = i * 128 + tid;       // 0..2047
            const int c  = e >> 4;
            const int ru = e & 15;
            uint4 hv = *(const uint4*)(sT + c * 136 + ru * 8);
            size_t gi;
            if (EPI == E_KVP)
                gi = ((size_t)bz * Dd + cbase + c) * (size_t)Dd + rbase + ru * 8;
            else
                gi = ((size_t)bGl * Dd + cbase + c) * (size_t)Ss + s0 + ru * 8;
            *(uint4*)(Ch + gi) = hv;
        }
    }
}

// ---------------------------------------------------------------------------
// fp32 -> fp16 convert (8 elems/thread)
// ---------------------------------------------------------------------------
__global__ void tofp16_k(const float* __restrict__ x, __half* __restrict__ h)
{
    const size_t i = ((size_t)blockIdx.x * 256 + threadIdx.x) * 8;
    float4 a = *(const float4*)(x + i);
    float4 b = *(const float4*)(x + i + 4);
    uint4 o;
    o.x = pack2h(__float2half_rn(a.x), __float2half_rn(a.y));
    o.y = pack2h(__float2half_rn(a.z), __float2half_rn(a.w));
    o.z = pack2h(__float2half_rn(b.x), __float2half_rn(b.y));
    o.w = pack2h(__float2half_rn(b.z), __float2half_rn(b.w));
    *(uint4*)(h + i) = o;
}

// ---------------------------------------------------------------------------
// W [K,N] -> Wt [N,K] fp16 (smem tile transpose)
// ---------------------------------------------------------------------------
__global__ void wsplit_k(const float* __restrict__ Wq, const float* __restrict__ Wk,
                         const float* __restrict__ Wv, const float* __restrict__ Wo)
{
    __shared__ float t[32][33];
    const float* W = (blockIdx.z == 0) ? Wq : (blockIdx.z == 1) ? Wk
                   : (blockIdx.z == 2) ? Wv : Wo;
    __half* Th = g_Wt16 + (size_t)blockIdx.z * Dd * Dd;
    const int n0 = blockIdx.x * 32, k0 = blockIdx.y * 32;
    const int tx = threadIdx.x, ty = threadIdx.y;
    #pragma unroll
    for (int i = 0; i < 4; i++)
        t[ty + i * 8][tx] = W[(size_t)(k0 + ty + i * 8) * Dd + n0 + tx];
    __syncthreads();
    #pragma unroll
    for (int i = 0; i < 4; i++) {
        const int r = ty + i * 8;
        Th[(size_t)(n0 + r) * Dd + k0 + tx] = __float2half_rn(t[tx][r]);
    }
}

// ---------------------------------------------------------------------------
// k_sum[b,d] = sum_s k_phi^T[b,d,s]  (one warp per contiguous row)
// ---------------------------------------------------------------------------
__global__ void ksum_k()
{
    const int gw = (blockIdx.x * blockDim.x + threadIdx.x) >> 5;  // 0..4095
    const int lane = threadIdx.x & 31;
    const uint4* ph = (const uint4*)(g_kT16 + (size_t)gw * Ss);
    float s = 0.f;
    #pragma unroll 4
    for (int i = 0; i < 16; i++) {
        uint4 xh = ph[i * 32 + lane];
        const __half2* h2 = (const __half2*)&xh;
        #pragma unroll
        for (int t = 0; t < 4; t++) {
            float2 f = __half22float2(h2[t]);
            s += f.x + f.y;
        }
    }
    #pragma unroll
    for (int o = 16; o; o >>= 1) s += __shfl_xor_sync(0xffffffffu, s, o);
    if (lane == 0) g_ksum[gw] = s;
}

// ---------------------------------------------------------------------------
// z[b,s] = 1 / (dot(q_phi[b,s,:], k_sum[b,:]) + 1e-6)
// ---------------------------------------------------------------------------
__global__ void z_k()
{
    const int gw = (blockIdx.x * blockDim.x + threadIdx.x) >> 5;  // 0..16383
    const int lane = threadIdx.x & 31;
    const int b = gw >> 12;
    const uint4* q4 = (const uint4*)(g_q16 + (size_t)gw * Dd);
    const float4* ks4 = (const float4*)(g_ksum + b * Dd);
    float s = 0.f;
    #pragma unroll
    for (int i = 0; i < 4; i++) {
        const int u = i * 32 + lane;
        uint4 xq = q4[u];
        float4 k0 = ks4[u * 2], k1 = ks4[u * 2 + 1];
        const __half2* h2 = (const __half2*)&xq;
        const float* kf = (const float*)&k0;
        #pragma unroll
        for (int t = 0; t < 2; t++) {
            float2 f = __half22float2(h2[t]);
            s += f.x * kf[t * 2] + f.y * kf[t * 2 + 1];
        }
        const float* kg = (const float*)&k1;
        #pragma unroll
        for (int t = 0; t < 2; t++) {
            float2 f = __half22float2(h2[2 + t]);
            s += f.x * kg[t * 2] + f.y * kg[t * 2 + 1];
        }
    }
    #pragma unroll
    for (int o = 16; o; o >>= 1) s += __shfl_xor_sync(0xffffffffu, s, o);
    if (lane == 0) g_z[gw] = 1.0f / (s + 1e-6f);
}

// ---------------------------------------------------------------------------
// Launch
// ---------------------------------------------------------------------------
extern "C" void kernel_launch(void* const* d_in, const int* in_sizes, int n_in,
                              void* d_out, int out_size)
{
    (void)in_sizes; (void)n_in; (void)out_size;
    const float* inputs  = (const float*)d_in[0];
    const float* context = (const float*)d_in[1];
    const float* Wq = (const float*)d_in[2];
    const float* bq = (const float*)d_in[3];
    const float* Wk = (const float*)d_in[4];
    const float* bk = (const float*)d_in[5];
    const float* Wv = (const float*)d_in[6];
    const float* bv = (const float*)d_in[7];
    const float* Wo = (const float*)d_in[8];
    const float* bo = (const float*)d_in[9];
    float* out = (float*)d_out;

    __half *i16, *c16, *q16, *kT, *vT, *at, *kvT, *Wt;
    float *zp;
    cudaGetSymbolAddress((void**)&i16, g_i16);
    cudaGetSymbolAddress((void**)&c16, g_c16);
    cudaGetSymbolAddress((void**)&q16, g_q16);
    cudaGetSymbolAddress((void**)&kT,  g_kT16);
    cudaGetSymbolAddress((void**)&vT,  g_vT16);
    cudaGetSymbolAddress((void**)&at,  g_at16);
    cudaGetSymbolAddress((void**)&kvT, g_kvT16);
    cudaGetSymbolAddress((void**)&Wt,  g_Wt16);
    cudaGetSymbolAddress((void**)&zp,  g_z);

    cudaFuncSetAttribute(mma_gemm<E_Q>,   cudaFuncAttributeMaxDynamicSharedMemorySize, SMEM_DYN);
    cudaFuncSetAttribute(mma_gemm<E_K>,   cudaFuncAttributeMaxDynamicSharedMemorySize, SMEM_DYN);
    cudaFuncSetAttribute(mma_gemm<E_V>,   cudaFuncAttributeMaxDynamicSharedMemorySize, SMEM_DYN);
    cudaFuncSetAttribute(mma_gemm<E_KVP>, cudaFuncAttributeMaxDynamicSharedMemorySize, SMEM_DYN);
    cudaFuncSetAttribute(mma_gemm<E_ATT>, cudaFuncAttributeMaxDynamicSharedMemorySize, SMEM_DYN);
    cudaFuncSetAttribute(mma_gemm<E_OUT>, cudaFuncAttributeMaxDynamicSharedMemorySize, SMEM_DYN);

    const size_t DD2 = (size_t)Dd * Dd;
    const dim3 blk(128);

    // 0. Convert weights (transposed) and activations to fp16
    wsplit_k<<<dim3(32, 32, 4), dim3(32, 8)>>>(Wq, Wk, Wv, Wo);
    tofp16_k<<<8192, 256>>>(inputs,  i16);
    tofp16_k<<<8192, 256>>>(context, c16);

    // 1-3. Projections
    mma_gemm<E_Q><<<dim3(8, 128, 1), blk, SMEM_DYN>>>(
        i16, Wt, Dd, Dd, Dd, 0, 0, bq, nullptr, nullptr, nullptr, q16);
    mma_gemm<E_K><<<dim3(8, 128, 1), blk, SMEM_DYN>>>(
        c16, Wt + DD2, Dd, Dd, Dd, 0, 0, bk, nullptr, nullptr, nullptr, kT);
    mma_gemm<E_V><<<dim3(8, 128, 1), blk, SMEM_DYN>>>(
        c16, Wt + 2 * DD2, Dd, Dd, Dd, 0, 0, bv, nullptr, nullptr, nullptr, vT);

    // 4-5. k_sum, z
    ksum_k<<<512, 256>>>();
    z_k<<<2048, 256>>>();

    // 6. kv^T[b,e,d] = (k^T @ v)^T  (M=d rows, N=e cols, K=s)
    mma_gemm<E_KVP><<<dim3(8, 8, 4), blk, SMEM_DYN>>>(
        kT, vT, Ss, Ss, Ss,
        (long long)Dd * Ss, (long long)Dd * Ss,
        nullptr, nullptr, nullptr, nullptr, kvT);

    // 7. att[b,s,e] = (q_phi @ kv) * z * ATT_SCALE
    mma_gemm<E_ATT><<<dim3(8, 32, 4), blk, SMEM_DYN>>>(
        q16, kvT, Dd, Dd, Dd,
        (long long)Ss * Dd, (long long)Dd * Dd,
        nullptr, zp, nullptr, nullptr, at);

    // 8. out = (att_scaled @ Wo) / ATT_SCALE + bo + inputs
    mma_gemm<E_OUT><<<dim3(8, 128, 1), blk, SMEM_DYN>>>(
        at, Wt + 3 * DD2, Dd, Dd, Dd, 0, 0,
        bo, nullptr, inputs, out, nullptr);
}